// round 15
// baseline (speedup 1.0000x reference)
#include <cuda_runtime.h>
#include <cstdint>

#define BATCH  64
#define MROWS  2048
#define DIM    512
#define ROWB   (DIM * 4)                 // 2048 B per row
#define ITEMS  4096                      // (batch, chunk) pairs; 32 rows each
#define NBLK   592                       // 148 SMs x 4 CTAs = one balanced wave
#define STAGE_ROWS  8
#define STAGE_BYTES (STAGE_ROWS * ROWB)  // 16 KB
#define NSTAGE 2

// Per-batch packed best: (dist2_bits << 32) | (0xFFFFFFFF - m). Zero at module
// load; the 512th arriving warp resets it after the gather (graph-replay safe).
// Note: any legal packed value is > 0 (low word >= 0xFFFFF800), so 0 is a
// safe identity for atomicMax.
__device__ unsigned long long g_best[BATCH];
// Per-batch arrival counter: 64 chunks x 8 warps = 512 arrivals.
__device__ unsigned int g_count[BATCH];

static __device__ __forceinline__ uint32_t s2u(const void* p) {
    return (uint32_t)__cvta_generic_to_shared(p);
}
static __device__ __forceinline__ void mbar_init(uint32_t a, uint32_t cnt) {
    asm volatile("mbarrier.init.shared.b64 [%0], %1;" :: "r"(a), "r"(cnt) : "memory");
}
static __device__ __forceinline__ void mbar_expect_tx(uint32_t a, uint32_t bytes) {
    asm volatile("mbarrier.arrive.expect_tx.shared.b64 _, [%0], %1;"
                 :: "r"(a), "r"(bytes) : "memory");
}
static __device__ __forceinline__ void mbar_arrive(uint32_t a) {
    asm volatile("mbarrier.arrive.shared.b64 _, [%0];" :: "r"(a) : "memory");
}
static __device__ __forceinline__ void mbar_wait(uint32_t a, uint32_t ph) {
    asm volatile(
        "{\n\t.reg .pred P;\n\t"
        "WL_%=:\n\t"
        "mbarrier.try_wait.parity.acquire.cta.shared::cta.b64 P, [%0], %1, 0x989680;\n\t"
        "@P bra.uni WD_%=;\n\t"
        "bra.uni WL_%=;\n\t"
        "WD_%=:\n\t}"
        :: "r"(a), "r"(ph) : "memory");
}
static __device__ __forceinline__ void bulk_g2s(uint32_t dst, const void* src,
                                                uint32_t bytes, uint32_t mbar) {
    asm volatile(
        "cp.async.bulk.shared::cta.global.mbarrier::complete_tx::bytes [%0], [%1], %2, [%3];"
        :: "r"(dst), "l"(src), "r"(bytes), "r"(mbar) : "memory");
}

// Block = 288 threads: 8 consumer warps + 1 producer warp.
// Flat work: item = b*64 + chunk (32 rows = 4 stages of 8); block bx handles
// items bx, bx+592, ... -> per-SM load spread ~4% instead of 33%.
__global__ __launch_bounds__(288, 4) void knn_tma_kernel(
    const float* __restrict__ inputs,
    const float* __restrict__ buffer,
    float* __restrict__ out)
{
    __shared__ __align__(128) char stage_mem[NSTAGE * STAGE_BYTES];   // 32 KB
    __shared__ unsigned long long mbar_full[NSTAGE];
    __shared__ unsigned long long mbar_empty[NSTAGE];

    const int bx   = blockIdx.x;
    const int tid  = threadIdx.x;
    const int warp = tid >> 5;
    const int lane = tid & 31;

    if (tid == 0) {
        #pragma unroll
        for (int s = 0; s < NSTAGE; s++) {
            mbar_init(s2u(&mbar_full[s]), 1);    // producer expect-arrive
            mbar_init(s2u(&mbar_empty[s]), 8);   // one arrive per consumer warp
        }
    }
    __syncthreads();

    if (warp == 8) {
        // ---------------- producer (lane 0 issues) ----------------
        if (lane == 0) {
            int it = 0;                          // global stage index in block
            for (int item = bx; item < ITEMS; item += NBLK) {
                const char* src =
                    (const char*)buffer + (size_t)item * 32 * ROWB;
                #pragma unroll
                for (int sub = 0; sub < 4; sub++, it++) {
                    const int s = it & 1;
                    if (it >= NSTAGE)
                        mbar_wait(s2u(&mbar_empty[s]), ((it - NSTAGE) >> 1) & 1);
                    mbar_expect_tx(s2u(&mbar_full[s]), STAGE_BYTES);
                    bulk_g2s(s2u(stage_mem) + s * STAGE_BYTES,
                             src + (size_t)sub * STAGE_BYTES,
                             STAGE_BYTES, s2u(&mbar_full[s]));
                }
            }
        }
    } else {
        // ---------------- consumers: warp w reduces row w of each stage ----
        int it = 0;
        for (int item = bx; item < ITEMS; item += NBLK) {
            const int b     = item >> 6;
            const int chunk = item & 63;

            // Query into registers; LDG latency hidden by first full-wait.
            const float4* qp =
                reinterpret_cast<const float4*>(inputs + (size_t)b * DIM);
            float4 q0 = qp[lane];
            float4 q1 = qp[lane + 32];
            float4 q2 = qp[lane + 64];
            float4 q3 = qp[lane + 96];

            unsigned long long local = 0ULL;
            #pragma unroll
            for (int sub = 0; sub < 4; sub++, it++) {
                const int s = it & 1;
                mbar_wait(s2u(&mbar_full[s]), (it >> 1) & 1);

                const float4* row = reinterpret_cast<const float4*>(
                    stage_mem + s * STAGE_BYTES + warp * ROWB);

                float acc0 = 0.0f, acc1 = 0.0f, acc2 = 0.0f, acc3 = 0.0f;
                float4 v, q;
                float d;
                v = row[lane];      q = q0;
                d = v.x - q.x; acc0 = fmaf(d, d, acc0);
                d = v.y - q.y; acc1 = fmaf(d, d, acc1);
                d = v.z - q.z; acc2 = fmaf(d, d, acc2);
                d = v.w - q.w; acc3 = fmaf(d, d, acc3);
                v = row[lane + 32]; q = q1;
                d = v.x - q.x; acc0 = fmaf(d, d, acc0);
                d = v.y - q.y; acc1 = fmaf(d, d, acc1);
                d = v.z - q.z; acc2 = fmaf(d, d, acc2);
                d = v.w - q.w; acc3 = fmaf(d, d, acc3);
                v = row[lane + 64]; q = q2;
                d = v.x - q.x; acc0 = fmaf(d, d, acc0);
                d = v.y - q.y; acc1 = fmaf(d, d, acc1);
                d = v.z - q.z; acc2 = fmaf(d, d, acc2);
                d = v.w - q.w; acc3 = fmaf(d, d, acc3);
                v = row[lane + 96]; q = q3;
                d = v.x - q.x; acc0 = fmaf(d, d, acc0);
                d = v.y - q.y; acc1 = fmaf(d, d, acc1);
                d = v.z - q.z; acc2 = fmaf(d, d, acc2);
                d = v.w - q.w; acc3 = fmaf(d, d, acc3);
                float acc = (acc0 + acc1) + (acc2 + acc3);

                #pragma unroll
                for (int off = 16; off > 0; off >>= 1)
                    acc += __shfl_xor_sync(0xFFFFFFFFu, acc, off);
                // shfl consumed every lane's reads -> all LDS of this stage
                // are complete; lane 0 may release the buffer.
                if (lane == 0) mbar_arrive(s2u(&mbar_empty[s]));

                const int m = chunk * 32 + sub * STAGE_ROWS + warp;
                // dist2 >= 0 -> float bits order-preserving; ~m tie-breaks
                // to the smallest m (argmax first-index semantics).
                unsigned long long pack =
                    ((unsigned long long)__float_as_uint(acc) << 32) |
                    (unsigned long long)(0xFFFFFFFFu - (unsigned)m);
                local = (pack > local) ? pack : local;
            }

            // ---- per-warp commit for this item ----
            unsigned int old = 0;
            if (lane == 0) {
                atomicMax(&g_best[b], local);
                __threadfence();                  // best visible before count
                old = atomicAdd(&g_count[b], 1u);
            }
            old = __shfl_sync(0xFFFFFFFFu, old, 0);

            if (old == 511u) {                    // 512th arrival: finish batch b
                __threadfence();                  // acquire all g_best updates
                unsigned long long v = 0ULL;
                if (lane == 0) v = atomicAdd(&g_best[b], 0ULL);
                v = __shfl_sync(0xFFFFFFFFu, v, 0);
                const unsigned mwin = 0xFFFFFFFFu - (unsigned)(v & 0xFFFFFFFFu);

                const float4* srcr = reinterpret_cast<const float4*>(
                    buffer + ((size_t)b * MROWS + mwin) * DIM);
                float4* dst = reinterpret_cast<float4*>(out + (size_t)b * DIM);
                #pragma unroll
                for (int j = 0; j < 4; j++)
                    dst[lane + 32 * j] = srcr[lane + 32 * j];

                if (lane == 0) {                  // restore invariant for replay
                    g_best[b] = 0ULL;
                    g_count[b] = 0u;
                    __threadfence();
                }
            }
        }
    }
}

extern "C" void kernel_launch(void* const* d_in, const int* in_sizes, int n_in,
                              void* d_out, int out_size)
{
    const float* inputs = (const float*)d_in[0];   // [B, D]
    const float* buffer = (const float*)d_in[1];   // [B, M, D]
    float* out = (float*)d_out;                    // [B, D]

    knn_tma_kernel<<<NBLK, 288>>>(inputs, buffer, out);
}

// round 16
// speedup vs baseline: 1.1123x; 1.1123x over previous
#include <cuda_runtime.h>
#include <cstdint>

#define BATCH  64
#define MROWS  2048
#define DIM    512
#define ROWB   (DIM * 4)                 // 2048 B per row
#define ITEMS  4096                      // (batch, chunk) pairs; 32 rows each
#define NBLK   592                       // 148 SMs x 4 CTAs = one balanced wave
#define STAGE_ROWS  8
#define STAGE_BYTES (STAGE_ROWS * ROWB)  // 16 KB
#define NSTAGE 3

// Per-batch packed best: (dist2_bits << 32) | (0xFFFFFFFF - m). Zero at module
// load; the closing warp resets it after the gather (graph-replay safe).
// Any legal packed value is nonzero, so 0 is a safe identity for atomicMax.
__device__ unsigned long long g_best[BATCH];
// Per-batch item counter: 64 chunks per batch, one commit per chunk.
__device__ unsigned int g_count[BATCH];

static __device__ __forceinline__ unsigned long long umax64(
    unsigned long long a, unsigned long long b) { return a > b ? a : b; }

static __device__ __forceinline__ uint32_t s2u(const void* p) {
    return (uint32_t)__cvta_generic_to_shared(p);
}
static __device__ __forceinline__ void mbar_init(uint32_t a, uint32_t cnt) {
    asm volatile("mbarrier.init.shared.b64 [%0], %1;" :: "r"(a), "r"(cnt) : "memory");
}
static __device__ __forceinline__ void mbar_expect_tx(uint32_t a, uint32_t bytes) {
    asm volatile("mbarrier.arrive.expect_tx.shared.b64 _, [%0], %1;"
                 :: "r"(a), "r"(bytes) : "memory");
}
static __device__ __forceinline__ void mbar_arrive(uint32_t a) {
    asm volatile("mbarrier.arrive.shared.b64 _, [%0];" :: "r"(a) : "memory");
}
static __device__ __forceinline__ void mbar_wait(uint32_t a, uint32_t ph) {
    asm volatile(
        "{\n\t.reg .pred P;\n\t"
        "WL_%=:\n\t"
        "mbarrier.try_wait.parity.acquire.cta.shared::cta.b64 P, [%0], %1, 0x989680;\n\t"
        "@P bra.uni WD_%=;\n\t"
        "bra.uni WL_%=;\n\t"
        "WD_%=:\n\t}"
        :: "r"(a), "r"(ph) : "memory");
}
static __device__ __forceinline__ void bulk_g2s(uint32_t dst, const void* src,
                                                uint32_t bytes, uint32_t mbar) {
    asm volatile(
        "cp.async.bulk.shared::cta.global.mbarrier::complete_tx::bytes [%0], [%1], %2, [%3];"
        :: "r"(dst), "l"(src), "r"(bytes), "r"(mbar) : "memory");
}

// Block = 288 threads: 8 consumer warps + 1 producer warp.
// Flat work: item = b*64 + chunk (32 rows = 4 stages of 8); block bx handles
// items bx, bx+592, ... (6-7 items) -> per-SM load spread ~4%.
__global__ __launch_bounds__(288, 4) void knn_tma_kernel(
    const float* __restrict__ inputs,
    const float* __restrict__ buffer,
    float* __restrict__ out)
{
    __shared__ __align__(128) char stage_mem[NSTAGE * STAGE_BYTES];   // 48 KB
    __shared__ unsigned long long mbar_full[NSTAGE];
    __shared__ unsigned long long mbar_empty[NSTAGE];
    __shared__ unsigned long long wbest[2][8];   // double-buffered by item parity

    const int bx   = blockIdx.x;
    const int tid  = threadIdx.x;
    const int warp = tid >> 5;
    const int lane = tid & 31;

    if (tid == 0) {
        #pragma unroll
        for (int s = 0; s < NSTAGE; s++) {
            mbar_init(s2u(&mbar_full[s]), 1);    // producer expect-arrive
            mbar_init(s2u(&mbar_empty[s]), 8);   // one arrive per consumer warp
        }
    }
    __syncthreads();

    if (warp == 8) {
        // ---------------- producer (lane 0 issues) ----------------
        if (lane == 0) {
            int it = 0;                          // fill index
            for (int item = bx; item < ITEMS; item += NBLK) {
                const char* src =
                    (const char*)buffer + (size_t)item * 32 * ROWB;
                #pragma unroll
                for (int sub = 0; sub < 4; sub++, it++) {
                    const int s = it % NSTAGE;
                    if (it >= NSTAGE)
                        mbar_wait(s2u(&mbar_empty[s]),
                                  ((it - NSTAGE) / NSTAGE) & 1);
                    mbar_expect_tx(s2u(&mbar_full[s]), STAGE_BYTES);
                    bulk_g2s(s2u(stage_mem) + s * STAGE_BYTES,
                             src + (size_t)sub * STAGE_BYTES,
                             STAGE_BYTES, s2u(&mbar_full[s]));
                }
            }
        }
    } else {
        // ---------------- consumers: warp w reduces row w of each stage ----
        int it = 0;                              // stage index
        int ip = 0;                              // item parity
        for (int item = bx; item < ITEMS; item += NBLK, ip ^= 1) {
            const int b     = item >> 6;
            const int chunk = item & 63;

            // Query into registers; LDG latency hidden by first full-wait.
            const float4* qp =
                reinterpret_cast<const float4*>(inputs + (size_t)b * DIM);
            float4 q0 = qp[lane];
            float4 q1 = qp[lane + 32];
            float4 q2 = qp[lane + 64];
            float4 q3 = qp[lane + 96];

            unsigned long long local = 0ULL;
            #pragma unroll
            for (int sub = 0; sub < 4; sub++, it++) {
                const int s = it % NSTAGE;
                mbar_wait(s2u(&mbar_full[s]), ((it / NSTAGE) & 1));

                const float4* row = reinterpret_cast<const float4*>(
                    stage_mem + s * STAGE_BYTES + warp * ROWB);

                float acc0 = 0.0f, acc1 = 0.0f, acc2 = 0.0f, acc3 = 0.0f;
                float4 v; float d;
                v = row[lane];
                d = v.x - q0.x; acc0 = fmaf(d, d, acc0);
                d = v.y - q0.y; acc1 = fmaf(d, d, acc1);
                d = v.z - q0.z; acc2 = fmaf(d, d, acc2);
                d = v.w - q0.w; acc3 = fmaf(d, d, acc3);
                v = row[lane + 32];
                d = v.x - q1.x; acc0 = fmaf(d, d, acc0);
                d = v.y - q1.y; acc1 = fmaf(d, d, acc1);
                d = v.z - q1.z; acc2 = fmaf(d, d, acc2);
                d = v.w - q1.w; acc3 = fmaf(d, d, acc3);
                v = row[lane + 64];
                d = v.x - q2.x; acc0 = fmaf(d, d, acc0);
                d = v.y - q2.y; acc1 = fmaf(d, d, acc1);
                d = v.z - q2.z; acc2 = fmaf(d, d, acc2);
                d = v.w - q2.w; acc3 = fmaf(d, d, acc3);
                v = row[lane + 96];
                d = v.x - q3.x; acc0 = fmaf(d, d, acc0);
                d = v.y - q3.y; acc1 = fmaf(d, d, acc1);
                d = v.z - q3.z; acc2 = fmaf(d, d, acc2);
                d = v.w - q3.w; acc3 = fmaf(d, d, acc3);
                float acc = (acc0 + acc1) + (acc2 + acc3);

                #pragma unroll
                for (int off = 16; off > 0; off >>= 1)
                    acc += __shfl_xor_sync(0xFFFFFFFFu, acc, off);
                // shfl consumed every lane's smem reads; release the buffer.
                if (lane == 0) mbar_arrive(s2u(&mbar_empty[s]));

                const int m = chunk * 32 + sub * STAGE_ROWS + warp;
                // dist2 >= 0 -> float bits order-preserving; ~m tie-breaks
                // to the smallest m (argmax first-index semantics).
                unsigned long long pack =
                    ((unsigned long long)__float_as_uint(acc) << 32) |
                    (unsigned long long)(0xFFFFFFFFu - (unsigned)m);
                local = umax64(local, pack);
            }

            // ---- one commit per item per block (warp 0 only) ----
            if (lane == 0) wbest[ip][warp] = local;
            asm volatile("bar.sync 1, 256;" ::: "memory");   // consumers only

            if (warp == 0) {
                unsigned long long blk = wbest[ip][0];
                #pragma unroll
                for (int w = 1; w < 8; w++) blk = umax64(blk, wbest[ip][w]);

                unsigned int old = 0;
                if (lane == 0) {
                    atomicMax(&g_best[b], blk);
                    __threadfence();              // best visible before count
                    old = atomicAdd(&g_count[b], 1u);
                }
                old = __shfl_sync(0xFFFFFFFFu, old, 0);

                if (old == 63u) {                 // final item of batch b
                    __threadfence();              // acquire all g_best updates
                    unsigned long long v = 0ULL;
                    if (lane == 0) v = atomicAdd(&g_best[b], 0ULL);
                    v = __shfl_sync(0xFFFFFFFFu, v, 0);
                    const unsigned mwin =
                        0xFFFFFFFFu - (unsigned)(v & 0xFFFFFFFFu);

                    const float4* srcr = reinterpret_cast<const float4*>(
                        buffer + ((size_t)b * MROWS + mwin) * DIM);
                    float4* dst =
                        reinterpret_cast<float4*>(out + (size_t)b * DIM);
                    #pragma unroll
                    for (int j = 0; j < 4; j++)
                        dst[lane + 32 * j] = srcr[lane + 32 * j];

                    if (lane == 0) {              // restore invariant for replay
                        g_best[b] = 0ULL;
                        g_count[b] = 0u;
                        __threadfence();
                    }
                }
            }
        }
    }
}

extern "C" void kernel_launch(void* const* d_in, const int* in_sizes, int n_in,
                              void* d_out, int out_size)
{
    const float* inputs = (const float*)d_in[0];   // [B, D]
    const float* buffer = (const float*)d_in[1];   // [B, M, D]
    float* out = (float*)d_out;                    // [B, D]

    knn_tma_kernel<<<NBLK, 288>>>(inputs, buffer, out);
}

// round 17
// speedup vs baseline: 1.7184x; 1.5449x over previous
#include <cuda_runtime.h>
#include <cstdint>

#define BATCH  64
#define MROWS  2048
#define DIM    512
#define ROWB   (DIM * 4)                 // 2048 B per row
#define NSEG   8                         // blocks per batch (64 % 8 == 0)
#define NCHUNK 64                        // chunks of 32 rows
#define CPB    (NCHUNK / NSEG)           // 8 chunks per block
#define STAGE_ROWS  8
#define STAGE_BYTES (STAGE_ROWS * ROWB)  // 16 KB
#define NSTAGE 3
#define NSTAGES_TOTAL (CPB * 4)          // 32 stages of 8 rows per block

// Per-(batch,seg) packed partial: (dist2_bits << 32) | (0xFFFFFFFF - m).
__device__ unsigned long long g_part[BATCH * NSEG];
// Per-batch completion counter; last block resets it (graph-replay safe).
__device__ unsigned int g_count[BATCH];

static __device__ __forceinline__ unsigned long long umax64(
    unsigned long long a, unsigned long long b) { return a > b ? a : b; }

static __device__ __forceinline__ uint32_t s2u(const void* p) {
    return (uint32_t)__cvta_generic_to_shared(p);
}
static __device__ __forceinline__ void mbar_init(uint32_t a, uint32_t cnt) {
    asm volatile("mbarrier.init.shared.b64 [%0], %1;" :: "r"(a), "r"(cnt) : "memory");
}
static __device__ __forceinline__ void mbar_expect_tx(uint32_t a, uint32_t bytes) {
    asm volatile("mbarrier.arrive.expect_tx.shared.b64 _, [%0], %1;"
                 :: "r"(a), "r"(bytes) : "memory");
}
static __device__ __forceinline__ void mbar_arrive(uint32_t a) {
    asm volatile("mbarrier.arrive.shared.b64 _, [%0];" :: "r"(a) : "memory");
}
static __device__ __forceinline__ void mbar_wait(uint32_t a, uint32_t ph) {
    asm volatile(
        "{\n\t.reg .pred P;\n\t"
        "WL_%=:\n\t"
        "mbarrier.try_wait.parity.acquire.cta.shared::cta.b64 P, [%0], %1, 0x989680;\n\t"
        "@P bra.uni WD_%=;\n\t"
        "bra.uni WL_%=;\n\t"
        "WD_%=:\n\t}"
        :: "r"(a), "r"(ph) : "memory");
}
static __device__ __forceinline__ void bulk_g2s(uint32_t dst, const void* src,
                                                uint32_t bytes, uint32_t mbar) {
    asm volatile(
        "cp.async.bulk.shared::cta.global.mbarrier::complete_tx::bytes [%0], [%1], %2, [%3];"
        :: "r"(dst), "l"(src), "r"(bytes), "r"(mbar) : "memory");
}

// Grid: BATCH*NSEG = 512 blocks; block = 288 threads = 8 consumer warps + 1
// producer warp. Producer streams 16KB stages via cp.async.bulk into a
// 3-stage smem ring; consumer warp w reduces row w of each stage.
// Block (b,seg) handles chunks seg, seg+8, ..., all within batch b, so the
// query lives in registers loaded once per block.
__global__ __launch_bounds__(288, 4) void knn_tma_kernel(
    const float* __restrict__ inputs,
    const float* __restrict__ buffer,
    float* __restrict__ out)
{
    __shared__ __align__(128) char stage_mem[NSTAGE * STAGE_BYTES];   // 48 KB
    __shared__ unsigned long long mbar_full[NSTAGE];
    __shared__ unsigned long long mbar_empty[NSTAGE];
    __shared__ unsigned long long wbest[8];
    __shared__ unsigned int s_is_last;
    __shared__ unsigned int s_m;

    const int bx   = blockIdx.x;
    const int b    = bx >> 3;                    // bx / NSEG
    const int seg  = bx & 7;                     // bx % NSEG
    const int tid  = threadIdx.x;
    const int warp = tid >> 5;
    const int lane = tid & 31;

    const float* buf_b = buffer + (size_t)b * MROWS * DIM;

    // Query into registers ONCE per block (single batch per block).
    // LDG latency hidden behind barrier init + first full-wait.
    const float4* qp = reinterpret_cast<const float4*>(inputs + (size_t)b * DIM);
    float4 q0 = qp[lane];
    float4 q1 = qp[lane + 32];
    float4 q2 = qp[lane + 64];
    float4 q3 = qp[lane + 96];

    if (tid == 0) {
        #pragma unroll
        for (int s = 0; s < NSTAGE; s++) {
            mbar_init(s2u(&mbar_full[s]), 1);     // producer's expect-arrive
            mbar_init(s2u(&mbar_empty[s]), 256);  // all consumer threads arrive
        }
    }
    __syncthreads();                              // barriers visible

    if (warp == 8) {
        // ---------------- producer (lane 0 only issues) ----------------
        if (lane == 0) {
            for (int it = 0; it < NSTAGES_TOTAL; it++) {
                const int s = it % NSTAGE;
                if (it >= NSTAGE) {
                    // buffer s reusable once consumers drained its previous use
                    mbar_wait(s2u(&mbar_empty[s]), ((it - NSTAGE) / NSTAGE) & 1);
                }
                const int t = it >> 2, sub = it & 3;
                const int row0 = (seg + t * NSEG) * 32 + sub * STAGE_ROWS;
                mbar_expect_tx(s2u(&mbar_full[s]), STAGE_BYTES);
                bulk_g2s(s2u(stage_mem) + s * STAGE_BYTES,
                         (const char*)buf_b + (size_t)row0 * ROWB,
                         STAGE_BYTES, s2u(&mbar_full[s]));
            }
        }
    } else {
        // ---------------- consumers: 8 warps, one row per warp/stage ----
        unsigned long long local = 0ULL;
        for (int it = 0; it < NSTAGES_TOTAL; it++) {
            const int s = it % NSTAGE;
            mbar_wait(s2u(&mbar_full[s]), (it / NSTAGE) & 1);

            const float4* row = reinterpret_cast<const float4*>(
                stage_mem + s * STAGE_BYTES + warp * ROWB);

            float acc0 = 0.0f, acc1 = 0.0f, acc2 = 0.0f, acc3 = 0.0f;
            float4 v; float d;
            v = row[lane];                        // LDS.128, conflict-free
            d = v.x - q0.x; acc0 = fmaf(d, d, acc0);
            d = v.y - q0.y; acc1 = fmaf(d, d, acc1);
            d = v.z - q0.z; acc2 = fmaf(d, d, acc2);
            d = v.w - q0.w; acc3 = fmaf(d, d, acc3);
            v = row[lane + 32];
            d = v.x - q1.x; acc0 = fmaf(d, d, acc0);
            d = v.y - q1.y; acc1 = fmaf(d, d, acc1);
            d = v.z - q1.z; acc2 = fmaf(d, d, acc2);
            d = v.w - q1.w; acc3 = fmaf(d, d, acc3);
            v = row[lane + 64];
            d = v.x - q2.x; acc0 = fmaf(d, d, acc0);
            d = v.y - q2.y; acc1 = fmaf(d, d, acc1);
            d = v.z - q2.z; acc2 = fmaf(d, d, acc2);
            d = v.w - q2.w; acc3 = fmaf(d, d, acc3);
            v = row[lane + 96];
            d = v.x - q3.x; acc0 = fmaf(d, d, acc0);
            d = v.y - q3.y; acc1 = fmaf(d, d, acc1);
            d = v.z - q3.z; acc2 = fmaf(d, d, acc2);
            d = v.w - q3.w; acc3 = fmaf(d, d, acc3);
            float acc = (acc0 + acc1) + (acc2 + acc3);

            #pragma unroll
            for (int off = 16; off > 0; off >>= 1)
                acc += __shfl_xor_sync(0xFFFFFFFFu, acc, off);

            mbar_arrive(s2u(&mbar_empty[s]));     // reads done; buffer reusable

            const int t = it >> 2, sub = it & 3;
            const int m = (seg + t * NSEG) * 32 + sub * STAGE_ROWS + warp;
            // dist2 >= 0 -> float bits order-preserving; ~m tie-breaks to
            // the smallest m (argmax first-index semantics).
            unsigned long long pack =
                ((unsigned long long)__float_as_uint(acc) << 32) |
                (unsigned long long)(0xFFFFFFFFu - (unsigned)m);
            local = umax64(local, pack);
        }
        if (lane == 0) wbest[warp] = local;
    }
    __syncthreads();

    // ---- Block reduce + completion protocol ----
    if (tid == 0) {
        unsigned long long blk = wbest[0];
        #pragma unroll
        for (int w = 1; w < 8; w++) blk = umax64(blk, wbest[w]);
        g_part[b * NSEG + seg] = blk;
        __threadfence();                          // publish partial before count
        unsigned int old = atomicAdd(&g_count[b], 1u);
        s_is_last = (old == NSEG - 1) ? 1u : 0u;
    }
    __syncthreads();

    // ---- Last block for this batch: reduce 8 partials + gather winner ----
    if (s_is_last) {
        if (warp == 0) {
            __threadfence();                      // acquire partials
            unsigned long long mx =
                (lane < NSEG) ? g_part[b * NSEG + lane] : 0ULL;
            #pragma unroll
            for (int off = 16; off > 0; off >>= 1) {
                unsigned long long o = __shfl_xor_sync(0xFFFFFFFFu, mx, off);
                mx = umax64(mx, o);
            }
            if (lane == 0) {
                s_m = 0xFFFFFFFFu - (unsigned)(mx & 0xFFFFFFFFu);
                g_count[b] = 0;                   // restore invariant for replay
            }
        }
        __syncthreads();
        const unsigned m = s_m;
        const float4* src = reinterpret_cast<const float4*>(
            buffer + ((size_t)b * MROWS + m) * DIM);
        float4* dst = reinterpret_cast<float4*>(out + (size_t)b * DIM);
        if (tid < DIM / 4) dst[tid] = src[tid];
    }
}

extern "C" void kernel_launch(void* const* d_in, const int* in_sizes, int n_in,
                              void* d_out, int out_size)
{
    const float* inputs = (const float*)d_in[0];   // [B, D]
    const float* buffer = (const float*)d_in[1];   // [B, M, D]
    float* out = (float*)d_out;                    // [B, D]

    knn_tma_kernel<<<BATCH * NSEG, 288>>>(inputs, buffer, out);
}